// round 5
// baseline (speedup 1.0000x reference)
#include <cuda_runtime.h>
#include <cstdint>

// Problem constants
#define BB    32
#define CC    16
#define NNODE 64
#define TLEN  4096
#define OUTD  16
#define TTILE 128

typedef unsigned long long u64;

// Precomputed, f32x2-SPLATTED M: g_Mdup[(o*64+j)*64 + i] = (m, m) packed in u64,
// where m = sum_n U[i,n]*theta[n,o]*U[j,n]. 512 KB, L2-resident.
__device__ u64 g_Mdup[OUTD * NNODE * NNODE];

// ---------------------------------------------------------------------------
// Kernel 1: precompute splatted M. 65536 elements, 64-term sum each. Trivial.
// ---------------------------------------------------------------------------
__global__ void compute_M_kernel(const float* __restrict__ U,
                                 const float* __restrict__ theta) {
    int idx = blockIdx.x * 256 + threadIdx.x;   // 0..65535
    int o = idx >> 12;
    int j = (idx >> 6) & 63;
    int i = idx & 63;
    float acc = 0.f;
#pragma unroll
    for (int n = 0; n < 64; ++n) {
        acc += U[i * 64 + n] * theta[n * 16 + o] * U[j * 64 + n];
    }
    unsigned ui = __float_as_uint(acc);
    g_Mdup[idx] = ((u64)ui << 32) | (u64)ui;    // (m, m) splat
}

// ---------------------------------------------------------------------------
// Kernel 2: fused channel-sum + 16x (64x64 @ 64x128) GEMM, FFMA2 inner loop.
// Grid: (T/128, B). Block: 256 threads, 3 CTAs/SM (regs<=85, smem 72KB).
// Dynamic smem layout:
//   [0, 32768)      xs4: channel-summed x tile, float4 [64 rows][32 float4]
//   [32768, 73728)  mss: splatted M_o, u64, rg-block layout:
//                   value (j, i) at u64 index (j*8 + (i>>3))*10 + (i&7)
//                   80B rg-block stride -> the 4 distinct rg addresses in a
//                   warp land on disjoint banks (0,80,160,240 mod 128 =
//                   0,80,32,112) -> conflict-free LDS.128.
// ---------------------------------------------------------------------------
__global__ void __launch_bounds__(256, 3)
spectral_main_kernel(const float* __restrict__ x, float* __restrict__ y) {
    extern __shared__ char smem_raw[];
    float4* xs4 = (float4*)smem_raw;                 // 32 KB
    u64*    mss = (u64*)(smem_raw + 32768);          // 40 KB

    const int tid = threadIdx.x;
    const int b   = blockIdx.y;
    const int t0  = blockIdx.x * TTILE;

    // ---- Phase 1: channel sum into smem: xs[n][tl] = sum_c x[b,c,n,t0+tl]
#pragma unroll
    for (int k = 0; k < 8; ++k) {
        int eid = tid + k * 256;          // 0..2047
        int n   = eid >> 5;               // 0..63
        int tc  = eid & 31;               // float4 column 0..31
        const float4* px =
            (const float4*)(x + ((size_t)b * CC * NNODE + n) * TLEN + t0) + tc;
        float4 s = make_float4(0.f, 0.f, 0.f, 0.f);
#pragma unroll
        for (int c = 0; c < CC; ++c) {
            float4 v = px[(size_t)c * (NNODE * (TLEN / 4))];
            s.x += v.x; s.y += v.y; s.z += v.z; s.w += v.w;
        }
        xs4[eid] = s;
    }

    // Thread tile mapping: 8 row-groups (rg) x 32 t-groups (tg).
    // Warp covers 4 rg x 8 tg: m-loads broadcast (8 lanes/addr), x-loads span
    // one contiguous 128B window.
    const int w  = tid >> 5;
    const int l  = tid & 31;
    const int rg = ((w >> 2) << 2) + (l >> 3);   // 0..7  -> rows rg*8 .. rg*8+7
    const int tg = ((w & 3) << 3) + (l & 7);     // 0..31 -> t = tg*4 .. tg*4+3

    for (int o = 0; o < OUTD; ++o) {
        // Prefetch M_o into registers BEFORE the sync: the L2 read latency is
        // hidden behind the barrier wait + previous iteration's tail instead
        // of being serialized between the two syncs.
        const ulonglong2* gm2 = (const ulonglong2*)(g_Mdup + o * (NNODE * NNODE));
        ulonglong2 pv[8];
#pragma unroll
        for (int k = 0; k < 8; ++k) pv[k] = gm2[tid + k * 256];

        __syncthreads();   // xs ready (o==0) / previous reads of mss done (o>0)

        // scatter into rg-block layout
#pragma unroll
        for (int k = 0; k < 8; ++k) {
            int e  = tid + k * 256;           // ulonglong2 index 0..2047
            int u  = e << 1;                  // u64 index in (j,i) space
            int jj = u >> 6;
            int ii = u & 63;
            *(ulonglong2*)&mss[(jj * 8 + (ii >> 3)) * 10 + (ii & 7)] = pv[k];
        }
        __syncthreads();

        // 8 rows x 4 t as packed f32x2 accumulators (32 regs)
        u64 acc[8][2];
#pragma unroll
        for (int r = 0; r < 8; ++r) { acc[r][0] = 0ull; acc[r][1] = 0ull; }

#pragma unroll 2
        for (int j = 0; j < NNODE; ++j) {
            // x: xs[j][tg*4 .. tg*4+3] as one LDS.128 (two f32x2 lanes)
            ulonglong2 xv = *(const ulonglong2*)&xs4[j * 32 + tg];
            // m: 8 pre-splatted (m,m) pairs for rows rg*8..rg*8+7, 4x LDS.128,
            // broadcast within warp, conflict-free across rg (80B stride)
            const u64* mrow = &mss[(j * 8 + rg) * 10];
            ulonglong2 ma = *(const ulonglong2*)(mrow + 0);
            ulonglong2 mb = *(const ulonglong2*)(mrow + 2);
            ulonglong2 mc = *(const ulonglong2*)(mrow + 4);
            ulonglong2 me = *(const ulonglong2*)(mrow + 6);
            asm("fma.rn.f32x2 %0, %1, %2, %0;" : "+l"(acc[0][0]) : "l"(xv.x), "l"(ma.x));
            asm("fma.rn.f32x2 %0, %1, %2, %0;" : "+l"(acc[0][1]) : "l"(xv.y), "l"(ma.x));
            asm("fma.rn.f32x2 %0, %1, %2, %0;" : "+l"(acc[1][0]) : "l"(xv.x), "l"(ma.y));
            asm("fma.rn.f32x2 %0, %1, %2, %0;" : "+l"(acc[1][1]) : "l"(xv.y), "l"(ma.y));
            asm("fma.rn.f32x2 %0, %1, %2, %0;" : "+l"(acc[2][0]) : "l"(xv.x), "l"(mb.x));
            asm("fma.rn.f32x2 %0, %1, %2, %0;" : "+l"(acc[2][1]) : "l"(xv.y), "l"(mb.x));
            asm("fma.rn.f32x2 %0, %1, %2, %0;" : "+l"(acc[3][0]) : "l"(xv.x), "l"(mb.y));
            asm("fma.rn.f32x2 %0, %1, %2, %0;" : "+l"(acc[3][1]) : "l"(xv.y), "l"(mb.y));
            asm("fma.rn.f32x2 %0, %1, %2, %0;" : "+l"(acc[4][0]) : "l"(xv.x), "l"(mc.x));
            asm("fma.rn.f32x2 %0, %1, %2, %0;" : "+l"(acc[4][1]) : "l"(xv.y), "l"(mc.x));
            asm("fma.rn.f32x2 %0, %1, %2, %0;" : "+l"(acc[5][0]) : "l"(xv.x), "l"(mc.y));
            asm("fma.rn.f32x2 %0, %1, %2, %0;" : "+l"(acc[5][1]) : "l"(xv.y), "l"(mc.y));
            asm("fma.rn.f32x2 %0, %1, %2, %0;" : "+l"(acc[6][0]) : "l"(xv.x), "l"(me.x));
            asm("fma.rn.f32x2 %0, %1, %2, %0;" : "+l"(acc[6][1]) : "l"(xv.y), "l"(me.x));
            asm("fma.rn.f32x2 %0, %1, %2, %0;" : "+l"(acc[7][0]) : "l"(xv.x), "l"(me.y));
            asm("fma.rn.f32x2 %0, %1, %2, %0;" : "+l"(acc[7][1]) : "l"(xv.y), "l"(me.y));
        }

        // store: y[b,o,i,t0+tg*4 .. +3], one STG.128 per row, coalesced across tg
        float* ybase = y + (((size_t)b * OUTD + o) * NNODE) * TLEN + t0 + tg * 4;
#pragma unroll
        for (int r = 0; r < 8; ++r) {
            int i = rg * 8 + r;
            ulonglong2 v;
            v.x = acc[r][0];
            v.y = acc[r][1];
            *(ulonglong2*)(ybase + (size_t)i * TLEN) = v;
        }
    }
}

// ---------------------------------------------------------------------------
// kernel_launch: graph-capturable, allocation-free.
// Inputs (metadata order): x (B,C,N,T) f32, U (N,N) f32, theta (N,OUT) f32.
// Output: y (B,OUT,N,T) f32.
// ---------------------------------------------------------------------------
extern "C" void kernel_launch(void* const* d_in, const int* in_sizes, int n_in,
                              void* d_out, int out_size) {
    const float* x     = (const float*)d_in[0];
    const float* U     = (const float*)d_in[1];
    const float* theta = (const float*)d_in[2];
    float* y = (float*)d_out;

    // 72 KB dynamic smem (attribute set is idempotent, not a stream op)
    cudaFuncSetAttribute(spectral_main_kernel,
                         cudaFuncAttributeMaxDynamicSharedMemorySize, 73728);

    compute_M_kernel<<<256, 256>>>(U, theta);
    spectral_main_kernel<<<dim3(TLEN / TTILE, BB), 256, 73728>>>(x, y);
}

// round 7
// speedup vs baseline: 2.3338x; 2.3338x over previous
#include <cuda_runtime.h>
#include <cuda_bf16.h>
#include <cstdint>

#define BB 32
#define CC 16
#define NN 64
#define TL 4096
#define OO 16
#define TT 128   // t-tile per CTA

// B operand of every mma, precomputed in fragment-register layout:
// g_Bfrag[((o*8 + nt)*4 + ks)*32 + lane] = {hi_b0, hi_b1, lo_b0, lo_b1}
// where (nt, ks) tile the 64x64 M_o into n-tiles of 8 (i) and k-steps of 16 (j),
// and (b0, b1) follow the PTX m16n8k16 B-fragment mapping:
//   b0 holds k = ks*16 + tig*2 + {0,1}, b1 holds k = ks*16 + tig*2 + {8,9},
//   n = nt*8 + gid   (gid = lane>>2, tig = lane&3), low 16 bits = lower k.
// 256 KB total, L2-resident, broadcast across all warps/CTAs.
__device__ __align__(16) uint4 g_Bfrag[OO * 8 * 4 * 32];

// ---------------------------------------------------------------------------
// Kernel 1: precompute M in bf16 hi/lo fragment layout. 16384 threads, trivial.
// M[o][j][i] = sum_n U[i,n] * theta[n,o] * U[j,n]   (symmetric in i,j)
// ---------------------------------------------------------------------------
__global__ void compute_B_kernel(const float* __restrict__ U,
                                 const float* __restrict__ theta) {
    int idx  = blockIdx.x * 256 + threadIdx.x;   // 0..16383
    int lane = idx & 31;
    int ks   = (idx >> 5) & 3;
    int nt   = (idx >> 7) & 7;
    int o    = idx >> 10;
    int gid  = lane >> 2, tig = lane & 3;
    int n    = nt * 8 + gid;            // i
    int kb   = ks * 16 + tig * 2;       // base j

    float m[4];
#pragma unroll
    for (int p = 0; p < 4; ++p) {
        int j = kb + (p >> 1) * 8 + (p & 1);    // k0,k0+1,k0+8,k0+9
        float acc = 0.f;
#pragma unroll
        for (int q = 0; q < 64; ++q)
            acc += U[n * 64 + q] * theta[q * 16 + o] * U[j * 64 + q];
        m[p] = acc;
    }
    __nv_bfloat162 h0 = __floats2bfloat162_rn(m[0], m[1]);  // .x = low k
    __nv_bfloat162 h1 = __floats2bfloat162_rn(m[2], m[3]);
    float r0 = m[0] - __bfloat162float(h0.x);
    float r1 = m[1] - __bfloat162float(h0.y);
    float r2 = m[2] - __bfloat162float(h1.x);
    float r3 = m[3] - __bfloat162float(h1.y);
    __nv_bfloat162 l0 = __floats2bfloat162_rn(r0, r1);
    __nv_bfloat162 l1 = __floats2bfloat162_rn(r2, r3);

    uint4 v;
    v.x = *(unsigned*)&h0;
    v.y = *(unsigned*)&h1;
    v.z = *(unsigned*)&l0;
    v.w = *(unsigned*)&l1;
    g_Bfrag[idx] = v;
}

// ---------------------------------------------------------------------------
// mma.sync m16n8k16 bf16 (baseline PTX, works under compute_103)
// ---------------------------------------------------------------------------
__device__ __forceinline__ void mma16816(float* c, const unsigned* a,
                                         unsigned b0, unsigned b1) {
    asm volatile(
        "mma.sync.aligned.m16n8k16.row.col.f32.bf16.bf16.f32 "
        "{%0,%1,%2,%3}, {%4,%5,%6,%7}, {%8,%9}, {%0,%1,%2,%3};"
        : "+f"(c[0]), "+f"(c[1]), "+f"(c[2]), "+f"(c[3])
        : "r"(a[0]), "r"(a[1]), "r"(a[2]), "r"(a[3]), "r"(b0), "r"(b1));
}

// ---------------------------------------------------------------------------
// Kernel 2: per CTA = (b, 128-t tile), 128 threads (4 warps).
//  Phase 1: channel-sum x -> smem xs[j=64][t=128] f32 (pitch 132, STS.128,
//           conflict-free).
//  Phase 2: each warp loads its A fragments (t rows wid*32..+31, all j) ONCE,
//           bf16 hi/lo split, 64 regs; reused for all 16 o.
//  Phase 3: per o: B frags streamed via coalesced LDG.128 from g_Bfrag,
//           3-term mma accumulation, STG epilogue. Zero LDS in the hot loop.
// ---------------------------------------------------------------------------
#define PITCH 132   // floats per xs row (128 + 4 pad): makes both the STS.128
                    // fills and the per-instruction A-gather hit 32 distinct banks

__global__ void __launch_bounds__(128, 3)
spectral_hmma_kernel(const float* __restrict__ x, float* __restrict__ y) {
    __shared__ float xs[NN * PITCH];   // 33792 B

    const int tid = threadIdx.x;
    const int wid = tid >> 5;
    const int lane = tid & 31;
    const int gid = lane >> 2;
    const int tig = lane & 3;
    const int b   = blockIdx.y;
    const int t0  = blockIdx.x * TT;

    // ---- Phase 1: channel sum -> xs[j][t]
    // warp w, step k handles row j = 4k + w; lanes cover t as float4 -> STS.128
#pragma unroll
    for (int k = 0; k < 16; ++k) {
        int j  = 4 * k + wid;
        int tc = lane;                       // float4 column 0..31
        const float4* px =
            (const float4*)(x + ((size_t)b * CC * NN + j) * TL + t0) + tc;
        float4 s = make_float4(0.f, 0.f, 0.f, 0.f);
#pragma unroll
        for (int c = 0; c < CC; ++c) {
            float4 v = px[(size_t)c * (NN * (TL / 4))];
            s.x += v.x; s.y += v.y; s.z += v.z; s.w += v.w;
        }
        *(float4*)&xs[j * PITCH + tc * 4] = s;
    }
    __syncthreads();

    // ---- Phase 2: A fragments (held across the whole o loop)
    // A tile for warp w: rows t = wid*32 .. +31 (2 m-tiles of 16), cols j 0..63
    // (4 k-steps of 16). Fragment a0..a3 per (mt,ks); hi/lo bf16 split.
    unsigned Ahi[2][4][4], Alo[2][4][4];
    {
        const int tb = wid * 32;
#pragma unroll
        for (int mt = 0; mt < 2; ++mt) {
#pragma unroll
            for (int ks = 0; ks < 4; ++ks) {
                int j0 = ks * 16 + tig * 2;
                int r0 = tb + mt * 16 + gid;
#pragma unroll
                for (int p = 0; p < 4; ++p) {
                    // p: 0->(r0,j0) 1->(r0+8,j0) 2->(r0,j0+8) 3->(r0+8,j0+8)
                    int rr = r0 + (p & 1) * 8;
                    int jj = j0 + (p >> 1) * 8;
                    float f0 = xs[jj * PITCH + rr];
                    float f1 = xs[(jj + 1) * PITCH + rr];
                    __nv_bfloat162 h = __floats2bfloat162_rn(f0, f1);
                    float q0 = f0 - __bfloat162float(h.x);
                    float q1 = f1 - __bfloat162float(h.y);
                    __nv_bfloat162 l = __floats2bfloat162_rn(q0, q1);
                    Ahi[mt][ks][p] = *(unsigned*)&h;
                    Alo[mt][ks][p] = *(unsigned*)&l;
                }
            }
        }
    }

    // ---- Phase 3: per-o GEMM + store
    for (int o = 0; o < OO; ++o) {
        const uint4* bp = g_Bfrag + (size_t)o * (8 * 4 * 32) + lane;
        float* const yo = y + ((size_t)b * OO + o) * NN * TL + t0;

#pragma unroll
        for (int half = 0; half < 2; ++half) {
            float acc[4][2][4];
#pragma unroll
            for (int n4 = 0; n4 < 4; ++n4)
#pragma unroll
                for (int mt = 0; mt < 2; ++mt)
#pragma unroll
                    for (int r = 0; r < 4; ++r) acc[n4][mt][r] = 0.f;

#pragma unroll
            for (int n4 = 0; n4 < 4; ++n4) {
                int nt = half * 4 + n4;
                uint4 bf[4];
#pragma unroll
                for (int ks = 0; ks < 4; ++ks) bf[ks] = bp[(nt * 4 + ks) * 32];
#pragma unroll
                for (int mt = 0; mt < 2; ++mt) {
#pragma unroll
                    for (int ks = 0; ks < 4; ++ks) {
                        mma16816(acc[n4][mt], Ahi[mt][ks], bf[ks].x, bf[ks].y); // hi*hi
                        mma16816(acc[n4][mt], Ahi[mt][ks], bf[ks].z, bf[ks].w); // hi*lo
                        mma16816(acc[n4][mt], Alo[mt][ks], bf[ks].x, bf[ks].y); // lo*hi
                    }
                }
            }

            // epilogue: c0 -> (t = base+gid, i = i0), c1 -> i0+1,
            //           c2 -> t+8, c3 -> (i0+1, t+8)
#pragma unroll
            for (int n4 = 0; n4 < 4; ++n4) {
                int i0 = (half * 4 + n4) * 8 + tig * 2;
#pragma unroll
                for (int mt = 0; mt < 2; ++mt) {
                    int tr = wid * 32 + mt * 16 + gid;
                    float* yb = yo + (size_t)i0 * TL + tr;
                    yb[0]      = acc[n4][mt][0];
                    yb[TL]     = acc[n4][mt][1];
                    yb[8]      = acc[n4][mt][2];
                    yb[TL + 8] = acc[n4][mt][3];
                }
            }
        }
    }
}

// ---------------------------------------------------------------------------
// kernel_launch: graph-capturable, allocation-free.
// Inputs: x (B,C,N,T) f32, U (N,N) f32, theta (N,OUT) f32. Output y (B,OUT,N,T) f32.
// ---------------------------------------------------------------------------
extern "C" void kernel_launch(void* const* d_in, const int* in_sizes, int n_in,
                              void* d_out, int out_size) {
    const float* x     = (const float*)d_in[0];
    const float* U     = (const float*)d_in[1];
    const float* theta = (const float*)d_in[2];
    float* y = (float*)d_out;

    compute_B_kernel<<<64, 256>>>(U, theta);
    spectral_hmma_kernel<<<dim3(TL / TT, BB), 128>>>(x, y);
}

// round 8
// speedup vs baseline: 2.4253x; 1.0392x over previous
#include <cuda_runtime.h>
#include <cuda_bf16.h>
#include <cstdint>

#define BB 32
#define CC 16
#define NN 64
#define TL 4096
#define OO 16
#define TT 64    // t-tile per CTA

// B operand of every mma, precomputed in fragment-register layout:
// g_Bfrag[((o*8 + nt)*4 + ks)*32 + lane] = {hi_b0, hi_b1, lo_b0, lo_b1}
// (nt, ks) tile the 64x64 M_o into n-tiles of 8 (i) and k-steps of 16 (j);
// (b0, b1) follow the PTX m16n8k16 B-fragment mapping:
//   b0 holds k = ks*16 + tig*2 + {0,1}, b1 holds k = ks*16 + tig*2 + {8,9},
//   n = nt*8 + gid (gid = lane>>2, tig = lane&3), low 16 bits = lower k.
// 256 KB total, L2-resident, broadcast across all warps/CTAs.
__device__ __align__(16) uint4 g_Bfrag[OO * 8 * 4 * 32];

// ---------------------------------------------------------------------------
// Kernel 1: precompute M in bf16 hi/lo fragment layout. Trivial cost.
// M[o][j][i] = sum_n U[i,n] * theta[n,o] * U[j,n]   (symmetric in i,j)
// ---------------------------------------------------------------------------
__global__ void compute_B_kernel(const float* __restrict__ U,
                                 const float* __restrict__ theta) {
    int idx  = blockIdx.x * 256 + threadIdx.x;   // 0..16383
    int lane = idx & 31;
    int ks   = (idx >> 5) & 3;
    int nt   = (idx >> 7) & 7;
    int o    = idx >> 10;
    int gid  = lane >> 2, tig = lane & 3;
    int n    = nt * 8 + gid;            // i
    int kb   = ks * 16 + tig * 2;       // base j

    float m[4];
#pragma unroll
    for (int p = 0; p < 4; ++p) {
        int j = kb + (p >> 1) * 8 + (p & 1);    // k0,k0+1,k0+8,k0+9
        float acc = 0.f;
#pragma unroll
        for (int q = 0; q < 64; ++q)
            acc += U[n * 64 + q] * theta[q * 16 + o] * U[j * 64 + q];
        m[p] = acc;
    }
    __nv_bfloat162 h0 = __floats2bfloat162_rn(m[0], m[1]);  // .x = low k
    __nv_bfloat162 h1 = __floats2bfloat162_rn(m[2], m[3]);
    float r0 = m[0] - __bfloat162float(h0.x);
    float r1 = m[1] - __bfloat162float(h0.y);
    float r2 = m[2] - __bfloat162float(h1.x);
    float r3 = m[3] - __bfloat162float(h1.y);
    __nv_bfloat162 l0 = __floats2bfloat162_rn(r0, r1);
    __nv_bfloat162 l1 = __floats2bfloat162_rn(r2, r3);

    uint4 v;
    v.x = *(unsigned*)&h0;
    v.y = *(unsigned*)&h1;
    v.z = *(unsigned*)&l0;
    v.w = *(unsigned*)&l1;
    g_Bfrag[idx] = v;
}

// ---------------------------------------------------------------------------
// mma.sync m16n8k16 bf16 (baseline PTX, assembles under compute_103)
// ---------------------------------------------------------------------------
__device__ __forceinline__ void mma16816(float* c, const unsigned* a,
                                         unsigned b0, unsigned b1) {
    asm volatile(
        "mma.sync.aligned.m16n8k16.row.col.f32.bf16.bf16.f32 "
        "{%0,%1,%2,%3}, {%4,%5,%6,%7}, {%8,%9}, {%0,%1,%2,%3};"
        : "+f"(c[0]), "+f"(c[1]), "+f"(c[2]), "+f"(c[3])
        : "r"(a[0]), "r"(a[1]), "r"(a[2]), "r"(a[3]), "r"(b0), "r"(b1));
}

// ---------------------------------------------------------------------------
// Kernel 2: per CTA = (b, 64-t tile), 128 threads (4 warps), 5 CTAs/SM.
//  Phase 1: channel-sum x -> smem xs[j=64][t=64] f32 (pitch 68).
//  Phase 2: each warp loads its A fragments (one 16-row m-tile, all j) ONCE,
//           bf16 hi/lo split (32 regs), reused for all 16 o.
//  Phase 3: per o, stream nt=0..7 with ping-pong-prefetched B frags (LDG.128,
//           L2-resident), 12 mmas per nt, immediate streaming stores.
//           Zero LDS in the hot loop.
// ---------------------------------------------------------------------------
#define PITCH 68   // floats per xs row (64 + 4 pad): A-gather LDS.32 hits
                   // 32 distinct banks (tig*2*68 = tig*8 mod 32, + gid 0..7)

__global__ void __launch_bounds__(128, 5)
spectral_hmma_kernel(const float* __restrict__ x, float* __restrict__ y) {
    __shared__ float xs[NN * PITCH];   // 17408 B

    const int tid  = threadIdx.x;
    const int wid  = tid >> 5;
    const int lane = tid & 31;
    const int gid  = lane >> 2;
    const int tig  = lane & 3;
    const int b    = blockIdx.y;
    const int t0   = blockIdx.x * TT;

    // ---- Phase 1: channel sum -> xs[j][t]
    // step k: warp w handles rows j = 8k + 2w + {0,1}; 16 lanes per row (float4)
#pragma unroll
    for (int k = 0; k < 8; ++k) {
        int eid = tid + k * 128;            // 0..1023 float4 elements
        int j   = eid >> 4;
        int tc  = eid & 15;                 // float4 column 0..15
        const float4* px =
            (const float4*)(x + ((size_t)b * CC * NN + j) * TL + t0) + tc;
        float4 s = make_float4(0.f, 0.f, 0.f, 0.f);
#pragma unroll
        for (int c = 0; c < CC; ++c) {
            float4 v = __ldcs(px + (size_t)c * (NN * (TL / 4)));
            s.x += v.x; s.y += v.y; s.z += v.z; s.w += v.w;
        }
        *(float4*)&xs[j * PITCH + tc * 4] = s;
    }
    __syncthreads();

    // ---- Phase 2: A fragments (held across the whole o loop)
    // Warp w owns m-tile rows t = wid*16 .. +15, cols j 0..63 (4 k-steps).
    unsigned Ahi[4][4], Alo[4][4];
    {
        const int r0 = wid * 16 + gid;
#pragma unroll
        for (int ks = 0; ks < 4; ++ks) {
            int j0 = ks * 16 + tig * 2;
#pragma unroll
            for (int p = 0; p < 4; ++p) {
                // p: 0->(r0,j0) 1->(r0+8,j0) 2->(r0,j0+8) 3->(r0+8,j0+8)
                int rr = r0 + (p & 1) * 8;
                int jj = j0 + (p >> 1) * 8;
                float f0 = xs[jj * PITCH + rr];
                float f1 = xs[(jj + 1) * PITCH + rr];
                __nv_bfloat162 h = __floats2bfloat162_rn(f0, f1);
                float q0 = f0 - __bfloat162float(h.x);
                float q1 = f1 - __bfloat162float(h.y);
                __nv_bfloat162 l = __floats2bfloat162_rn(q0, q1);
                Ahi[ks][p] = *(unsigned*)&h;
                Alo[ks][p] = *(unsigned*)&l;
            }
        }
    }

    // ---- Phase 3: per-o GEMM + streaming store
    const int tr = wid * 16 + gid;          // this thread's t row (c0/c1)
    for (int o = 0; o < OO; ++o) {
        const uint4* bp = g_Bfrag + (size_t)o * (8 * 4 * 32) + lane;
        float* const yo = y + ((size_t)b * OO + o) * NN * TL + t0 + tr;

        uint4 bfA[4], bfB[4];
#pragma unroll
        for (int ks = 0; ks < 4; ++ks) bfA[ks] = bp[ks * 32];   // nt = 0

#pragma unroll
        for (int nt = 0; nt < 8; ++nt) {
            const uint4* cur = (nt & 1) ? bfB : bfA;
            uint4*       nxt = (nt & 1) ? bfA : bfB;
            if (nt < 7) {
#pragma unroll
                for (int ks = 0; ks < 4; ++ks)
                    nxt[ks] = bp[((nt + 1) * 4 + ks) * 32];
            }

            float acc[4] = {0.f, 0.f, 0.f, 0.f};
#pragma unroll
            for (int ks = 0; ks < 4; ++ks) {
                mma16816(acc, Ahi[ks], cur[ks].x, cur[ks].y);  // hi*hi
                mma16816(acc, Ahi[ks], cur[ks].z, cur[ks].w);  // hi*lo
                mma16816(acc, Alo[ks], cur[ks].x, cur[ks].y);  // lo*hi
            }

            // c0 -> (i0, t), c1 -> (i0+1, t), c2 -> (i0, t+8), c3 -> (i0+1, t+8)
            int i0 = nt * 8 + tig * 2;
            float* yb = yo + (size_t)i0 * TL;
            __stcs(yb,          acc[0]);
            __stcs(yb + TL,     acc[1]);
            __stcs(yb + 8,      acc[2]);
            __stcs(yb + TL + 8, acc[3]);
        }
    }
}

// ---------------------------------------------------------------------------
// kernel_launch: graph-capturable, allocation-free.
// Inputs: x (B,C,N,T) f32, U (N,N) f32, theta (N,OUT) f32. Output y (B,OUT,N,T) f32.
// ---------------------------------------------------------------------------
extern "C" void kernel_launch(void* const* d_in, const int* in_sizes, int n_in,
                              void* d_out, int out_size) {
    const float* x     = (const float*)d_in[0];
    const float* U     = (const float*)d_in[1];
    const float* theta = (const float*)d_in[2];
    float* y = (float*)d_out;

    compute_B_kernel<<<64, 256>>>(U, theta);
    spectral_hmma_kernel<<<dim3(TL / TT, BB), 128>>>(x, y);
}

// round 9
// speedup vs baseline: 2.6288x; 1.0839x over previous
#include <cuda_runtime.h>
#include <cuda_bf16.h>
#include <cstdint>

#define BB 32
#define CC 16
#define NN 64
#define TL 4096
#define OO 16
#define TT 128   // t-tile per CTA

// B operand of every mma, precomputed in fragment-register layout:
// g_Bfrag[((o*8 + nt)*4 + ks)*32 + lane] = {hi_b0, hi_b1, lo_b0, lo_b1}
// (nt, ks) tile the 64x64 M_o into n-tiles of 8 (i) and k-steps of 16 (j);
// (b0, b1) follow the PTX m16n8k16 B-fragment mapping:
//   b0 holds k = ks*16 + tig*2 + {0,1}, b1 holds k = ks*16 + tig*2 + {8,9},
//   n = nt*8 + gid (gid = lane>>2, tig = lane&3), low 16 bits = lower k.
// 256 KB total, L2-resident, broadcast across all warps/CTAs.
__device__ __align__(16) uint4 g_Bfrag[OO * 8 * 4 * 32];

// ---------------------------------------------------------------------------
// Kernel 1: precompute M in bf16 hi/lo fragment layout (smem-staged U/theta).
// M[o][j][i] = sum_n U[i,n] * theta[n,o] * U[j,n]
// ---------------------------------------------------------------------------
__global__ void compute_B_kernel(const float* __restrict__ U,
                                 const float* __restrict__ theta) {
    __shared__ float sU[64 * 64];    // 16 KB
    __shared__ float sT[64 * 16];    // 4 KB
    int t = threadIdx.x;
    for (int i = t; i < 4096; i += 256) sU[i] = U[i];
    for (int i = t; i < 1024; i += 256) sT[i] = theta[i];
    __syncthreads();

    int idx  = blockIdx.x * 256 + t;            // 0..16383
    int lane = idx & 31;
    int ks   = (idx >> 5) & 3;
    int nt   = (idx >> 7) & 7;
    int o    = idx >> 10;
    int gid  = lane >> 2, tig = lane & 3;
    int n    = nt * 8 + gid;            // i
    int kb   = ks * 16 + tig * 2;       // base j

    int j0 = kb, j1 = kb + 1, j2 = kb + 8, j3 = kb + 9;
    float a0 = 0.f, a1 = 0.f, a2 = 0.f, a3 = 0.f;
#pragma unroll
    for (int q = 0; q < 64; ++q) {
        float un = sU[n * 64 + q] * sT[q * 16 + o];
        a0 += un * sU[j0 * 64 + q];
        a1 += un * sU[j1 * 64 + q];
        a2 += un * sU[j2 * 64 + q];
        a3 += un * sU[j3 * 64 + q];
    }
    __nv_bfloat162 h0 = __floats2bfloat162_rn(a0, a1);  // .x = low k
    __nv_bfloat162 h1 = __floats2bfloat162_rn(a2, a3);
    __nv_bfloat162 l0 = __floats2bfloat162_rn(a0 - __bfloat162float(h0.x),
                                              a1 - __bfloat162float(h0.y));
    __nv_bfloat162 l1 = __floats2bfloat162_rn(a2 - __bfloat162float(h1.x),
                                              a3 - __bfloat162float(h1.y));
    uint4 v;
    v.x = *(unsigned*)&h0;
    v.y = *(unsigned*)&h1;
    v.z = *(unsigned*)&l0;
    v.w = *(unsigned*)&l1;
    g_Bfrag[idx] = v;
}

// ---------------------------------------------------------------------------
// mma.sync m16n8k16 bf16 (baseline PTX, assembles under compute_103)
// ---------------------------------------------------------------------------
__device__ __forceinline__ void mma16816(float* c, const unsigned* a,
                                         unsigned b0, unsigned b1) {
    asm volatile(
        "mma.sync.aligned.m16n8k16.row.col.f32.bf16.bf16.f32 "
        "{%0,%1,%2,%3}, {%4,%5,%6,%7}, {%8,%9}, {%0,%1,%2,%3};"
        : "+f"(c[0]), "+f"(c[1]), "+f"(c[2]), "+f"(c[3])
        : "r"(a[0]), "r"(a[1]), "r"(a[2]), "r"(a[3]), "r"(b0), "r"(b1));
}

// ---------------------------------------------------------------------------
// Kernel 2: per CTA = (b, 128-t tile), 128 threads (4 warps), 4 CTAs/SM.
//  Phase 1: channel-sum x -> smem xs[j=64][t=128] f32 (pitch 132).
//  Phase 2: each warp loads A fragments for TWO 16-row m-tiles (32 t rows),
//           bf16 hi/lo split (64 regs), reused for all 16 o. The 2x m-tiles
//           halve B-fragment traffic per output byte vs 1 m-tile/warp.
//  Phase 3: per o, stream nt=0..7 with ping-pong-prefetched B frags
//           (LDG.128, L1/L2-resident), 24 mmas per nt, streaming stores.
//           Zero LDS in the hot loop.
// ---------------------------------------------------------------------------
#define PITCH 132   // floats per xs row (128 + 4 pad): STS.128 fills and the
                    // A-gather LDS.32 both hit 32 distinct banks

__global__ void __launch_bounds__(128, 4)
spectral_hmma_kernel(const float* __restrict__ x, float* __restrict__ y) {
    __shared__ float xs[NN * PITCH];   // 33792 B

    const int tid  = threadIdx.x;
    const int wid  = tid >> 5;
    const int lane = tid & 31;
    const int gid  = lane >> 2;
    const int tig  = lane & 3;
    const int b    = blockIdx.y;
    const int t0   = blockIdx.x * TT;

    // ---- Phase 1: channel sum -> xs[j][t]
#pragma unroll
    for (int k = 0; k < 16; ++k) {
        int eid = tid + k * 128;            // 0..2047 float4 elements
        int j   = eid >> 5;
        int tc  = eid & 31;                 // float4 column 0..31
        const float4* px =
            (const float4*)(x + ((size_t)b * CC * NN + j) * TL + t0) + tc;
        float4 s = make_float4(0.f, 0.f, 0.f, 0.f);
#pragma unroll
        for (int c = 0; c < CC; ++c) {
            float4 v = __ldcs(px + (size_t)c * (NN * (TL / 4)));
            s.x += v.x; s.y += v.y; s.z += v.z; s.w += v.w;
        }
        *(float4*)&xs[j * PITCH + tc * 4] = s;
    }
    __syncthreads();

    // ---- Phase 2: A fragments, 2 m-tiles per warp (t rows wid*32 .. +31)
    unsigned Ahi[2][4][4], Alo[2][4][4];
    {
        const int tb = wid * 32;
#pragma unroll
        for (int mt = 0; mt < 2; ++mt) {
#pragma unroll
            for (int ks = 0; ks < 4; ++ks) {
                int j0 = ks * 16 + tig * 2;
                int r0 = tb + mt * 16 + gid;
#pragma unroll
                for (int p = 0; p < 4; ++p) {
                    // p: 0->(r0,j0) 1->(r0+8,j0) 2->(r0,j0+8) 3->(r0+8,j0+8)
                    int rr = r0 + (p & 1) * 8;
                    int jj = j0 + (p >> 1) * 8;
                    float f0 = xs[jj * PITCH + rr];
                    float f1 = xs[(jj + 1) * PITCH + rr];
                    __nv_bfloat162 h = __floats2bfloat162_rn(f0, f1);
                    float q0 = f0 - __bfloat162float(h.x);
                    float q1 = f1 - __bfloat162float(h.y);
                    __nv_bfloat162 l = __floats2bfloat162_rn(q0, q1);
                    Ahi[mt][ks][p] = *(unsigned*)&h;
                    Alo[mt][ks][p] = *(unsigned*)&l;
                }
            }
        }
    }

    // ---- Phase 3: per-o GEMM + streaming store
    for (int o = 0; o < OO; ++o) {
        const uint4* bp = g_Bfrag + (size_t)o * (8 * 4 * 32) + lane;
        float* const yo = y + ((size_t)b * OO + o) * NN * TL + t0;

        uint4 bfA[4], bfB[4];
#pragma unroll
        for (int ks = 0; ks < 4; ++ks) bfA[ks] = bp[ks * 32];   // nt = 0

#pragma unroll
        for (int nt = 0; nt < 8; ++nt) {
            const uint4* cur = (nt & 1) ? bfB : bfA;
            uint4*       nxt = (nt & 1) ? bfA : bfB;
            if (nt < 7) {
#pragma unroll
                for (int ks = 0; ks < 4; ++ks)
                    nxt[ks] = bp[((nt + 1) * 4 + ks) * 32];
            }

            float acc[2][4] = {{0.f, 0.f, 0.f, 0.f}, {0.f, 0.f, 0.f, 0.f}};
#pragma unroll
            for (int ks = 0; ks < 4; ++ks) {
#pragma unroll
                for (int mt = 0; mt < 2; ++mt) {
                    mma16816(acc[mt], Ahi[mt][ks], cur[ks].x, cur[ks].y); // hi*hi
                    mma16816(acc[mt], Ahi[mt][ks], cur[ks].z, cur[ks].w); // hi*lo
                    mma16816(acc[mt], Alo[mt][ks], cur[ks].x, cur[ks].y); // lo*hi
                }
            }

            // c0 -> (i0, t), c1 -> (i0+1, t), c2 -> (i0, t+8), c3 -> (i0+1, t+8)
            int i0 = nt * 8 + tig * 2;
#pragma unroll
            for (int mt = 0; mt < 2; ++mt) {
                int tr = wid * 32 + mt * 16 + gid;
                float* yb = yo + (size_t)i0 * TL + tr;
                __stcs(yb,          acc[mt][0]);
                __stcs(yb + TL,     acc[mt][1]);
                __stcs(yb + 8,      acc[mt][2]);
                __stcs(yb + TL + 8, acc[mt][3]);
            }
        }
    }
}

// ---------------------------------------------------------------------------
// kernel_launch: graph-capturable, allocation-free.
// Inputs: x (B,C,N,T) f32, U (N,N) f32, theta (N,OUT) f32. Output y (B,OUT,N,T) f32.
// ---------------------------------------------------------------------------
extern "C" void kernel_launch(void* const* d_in, const int* in_sizes, int n_in,
                              void* d_out, int out_size) {
    const float* x     = (const float*)d_in[0];
    const float* U     = (const float*)d_in[1];
    const float* theta = (const float*)d_in[2];
    float* y = (float*)d_out;

    compute_B_kernel<<<64, 256>>>(U, theta);
    spectral_hmma_kernel<<<dim3(TL / TT, BB), 128>>>(x, y);
}